// round 15
// baseline (speedup 1.0000x reference)
#include <cuda_runtime.h>
#include <cuda_bf16.h>
#include <math.h>
#include <stdint.h>

typedef __nv_bfloat16 bf16;

#define BQ   16384
#define OBSD 512
#define HD   1024
#define NHEADCOLS 2048
#define NAG  9

// ---------------- scratch (device globals: no allocation allowed) ----------------
__device__ bf16  g_obs[BQ * OBSD];        // 16 MB
__device__ bf16  g_W1 [OBSD * HD];        // 1 MB
__device__ bf16  g_W2 [HD * HD];          // 2 MB
__device__ bf16  g_Wh [HD * NHEADCOLS];   // 4 MB  (Wc1 | Wt1 | Wk1[:H]+Wk1[H:])
__device__ bf16  g_G1 [BQ * HD];          // 32 MB
__device__ bf16  g_G  [BQ * HD];          // 32 MB
__device__ float g_wvec [NHEADCOLS];      // Wc2 | Wt2 | Wk2
__device__ float g_bhead[NHEADCOLS];      // bc1 | bt1 | bk1
__device__ float g_logits[BQ * 3];

// ---------------- small helper kernels ----------------
__global__ void k_prep(const float* __restrict__ W1, const float* __restrict__ W2,
                       const float* __restrict__ Wc1, const float* __restrict__ Wt1,
                       const float* __restrict__ Wk1,
                       const float* __restrict__ Wc2, const float* __restrict__ Wt2,
                       const float* __restrict__ Wk2,
                       const float* __restrict__ bc1, const float* __restrict__ bt1,
                       const float* __restrict__ bk1)
{
    int i = blockIdx.x * blockDim.x + threadIdx.x;
    if (i < OBSD * HD) g_W1[i] = __float2bfloat16(W1[i]);
    if (i < HD * HD)   g_W2[i] = __float2bfloat16(W2[i]);
    if (i < HD * NHEADCOLS) {
        int k = i >> 11;        // row (0..1023)
        int j = i & 2047;       // col (0..2047)
        float v;
        if (j < 512)          v = Wc1[k * 512 + j];
        else if (j < 1024)    v = Wt1[k * 512 + (j - 512)];
        else                  v = Wk1[k * 1024 + (j - 1024)] + Wk1[(1024 + k) * 1024 + (j - 1024)];
        g_Wh[i] = __float2bfloat16(v);
    }
    if (i < NHEADCOLS) {
        float wv, bh;
        if (i < 512)       { wv = Wc2[i];        bh = bc1[i]; }
        else if (i < 1024) { wv = Wt2[i - 512];  bh = bt1[i - 512]; }
        else               { wv = Wk2[i - 1024]; bh = bk1[i - 1024]; }
        g_wvec[i] = wv; g_bhead[i] = bh;
    }
    if (i < BQ * 3) g_logits[i] = 0.0f;
}

__global__ void k_conv_obs(const float4* __restrict__ in, __nv_bfloat162* __restrict__ out)
{
    int i = blockIdx.x * blockDim.x + threadIdx.x;
    if (i < BQ * OBSD / 4) {
        float4 v = in[i];
        out[2 * i]     = __floats2bfloat162_rn(v.x, v.y);
        out[2 * i + 1] = __floats2bfloat162_rn(v.z, v.w);
    }
}

__global__ void k_final(const float* __restrict__ logits,
                        const float* __restrict__ bc2, const float* __restrict__ bt2,
                        const float* __restrict__ bk2, float* __restrict__ out)
{
    int b = blockIdx.x * blockDim.x + threadIdx.x;
    if (b >= BQ) return;
    float cv = 1.0f / (1.0f + expf(-(logits[b * 3 + 0] + bc2[0])));
    float tk = 1.0f / (1.0f + expf(-(logits[b * 3 + 1] + bt2[0])));
    float cp = 1.0f / (1.0f + expf(-(logits[b * 3 + 2] + bk2[0])));
#pragma unroll
    for (int n = 0; n < NAG; ++n) {
        out[(size_t)0 * BQ * NAG + b * NAG + n] = cv;
        out[(size_t)1 * BQ * NAG + b * NAG + n] = tk;
        out[(size_t)2 * BQ * NAG + b * NAG + n] = cp;
    }
}

// --- bf16 tensor-core GEMM: 128x128 CTA, 8 warps of 64x32, BK=32, 4 stages, 2 CTAs/SM (16 warps) ---
#define BM 128
#define BN 128
#define BK 32
#define STAGES 4
#define A_LD 40               // 32 + 8 pad: 80B rows -> disjoint bank quads for 8-row ldmatrix
#define B_LD 136              // 128 + 8 pad
#define A_STAGE (BM * A_LD)   // 5120 elems
#define B_STAGE (BK * B_LD)   // 4352 elems
#define SMEM_BYTES (STAGES * (A_STAGE + B_STAGE) * 2)   // 75776 ; x2 CTAs = 151552 <= 228KB

__device__ __forceinline__ void cp16s(uint32_t dst, const void* src)
{
    asm volatile("cp.async.cg.shared.global [%0], [%1], 16;\n" :: "r"(dst), "l"(src));
}

__device__ __forceinline__ uint32_t smem_u32_of(const void* p)
{
    uint32_t a;
    asm("{ .reg .u64 t; cvta.to.shared.u64 t, %1; cvt.u32.u64 %0, t; }" : "=r"(a) : "l"(p));
    return a;
}

__device__ __forceinline__ void ldsm_x4(uint32_t& r0, uint32_t& r1, uint32_t& r2, uint32_t& r3, uint32_t addr)
{
    asm volatile("ldmatrix.sync.aligned.m8n8.x4.shared.b16 {%0,%1,%2,%3}, [%4];\n"
                 : "=r"(r0), "=r"(r1), "=r"(r2), "=r"(r3) : "r"(addr));
}

__device__ __forceinline__ void ldsm_x4t(uint32_t& r0, uint32_t& r1, uint32_t& r2, uint32_t& r3, uint32_t addr)
{
    asm volatile("ldmatrix.sync.aligned.m8n8.x4.trans.shared.b16 {%0,%1,%2,%3}, [%4];\n"
                 : "=r"(r0), "=r"(r1), "=r"(r2), "=r"(r3) : "r"(addr));
}

__device__ __forceinline__ void mma16816(float* c, const uint32_t* a, const uint32_t* b)
{
    asm volatile("mma.sync.aligned.m16n8k16.row.col.f32.bf16.bf16.f32 "
                 "{%0,%1,%2,%3}, {%4,%5,%6,%7}, {%8,%9}, {%0,%1,%2,%3};\n"
                 : "+f"(c[0]), "+f"(c[1]), "+f"(c[2]), "+f"(c[3])
                 : "r"(a[0]), "r"(a[1]), "r"(a[2]), "r"(a[3]), "r"(b[0]), "r"(b[1]));
}

// EPI 0: C = relu(acc + bias[col]) -> bf16 Cout[M,N]
// EPI 1: per-row partial dot of relu(acc + bhead[col]) with wvec[col], atomicAdd -> logits[row*3+head]
template <int EPI>
__global__ void __launch_bounds__(256, 2)
gemm_bf16(const bf16* __restrict__ A, const bf16* __restrict__ Bw,
          const float* __restrict__ bias, bf16* __restrict__ Cout,
          const float* __restrict__ wvec, const float* __restrict__ bhead,
          float* __restrict__ logits, int M, int N, int K)
{
    extern __shared__ __align__(16) bf16 smem[];
    bf16* As = smem;                     // STAGES * A_STAGE
    bf16* Bs = smem + STAGES * A_STAGE;  // STAGES * B_STAGE

    const int t  = threadIdx.x;
    const int n0 = blockIdx.x * BN;
    const int m0 = blockIdx.y * BM;
    const int KT = K / BK;

    const uint32_t smA = smem_u32_of(As);
    const uint32_t smB = smem_u32_of(Bs);

    // ---- hoisted loader addressing (256 threads: 2 chunks each for A and B) ----
    const int arow_ld = t >> 2, acc_ld = t & 3;     // A rows 0..63 (+64 per i), 4 chunks/row
    const int brow_ld = t >> 4, bcc_ld = t & 15;    // B rows 0..15 (+16 per i), 16 chunks/row
    const uint32_t dA0 = smA + (uint32_t)(arow_ld * A_LD + acc_ld * 8) * 2;
    const uint32_t dB0 = smB + (uint32_t)(brow_ld * B_LD + bcc_ld * 8) * 2;
    const bf16* sA0 = A + (size_t)(m0 + arow_ld) * K + acc_ld * 8;
    const bf16* sB0 = Bw + (size_t)brow_ld * N + n0 + bcc_ld * 8;

    auto load_stage = [&](int s, int kt) {
        const uint32_t dA = dA0 + (uint32_t)s * (A_STAGE * 2);
        const bf16*    sA = sA0 + kt * BK;
#pragma unroll
        for (int i = 0; i < 2; i++)
            cp16s(dA + i * (64 * A_LD * 2), sA + (size_t)i * 64 * K);
        const uint32_t dB = dB0 + (uint32_t)s * (B_STAGE * 2);
        const bf16*    sB = sB0 + (size_t)kt * BK * N;
#pragma unroll
        for (int i = 0; i < 2; i++)
            cp16s(dB + i * (16 * B_LD * 2), sB + (size_t)i * 16 * N);
    };

    // prefetch 3 stages
    load_stage(0, 0);
    asm volatile("cp.async.commit_group;\n" ::: "memory");
    load_stage(1, 1);
    asm volatile("cp.async.commit_group;\n" ::: "memory");
    load_stage(2, 2);
    asm volatile("cp.async.commit_group;\n" ::: "memory");

    const int lane = t & 31;
    const int warp = t >> 5;
    const int wm = warp & 1;   // 2 warps along M (tile 64)
    const int wn = warp >> 1;  // 4 warps along N (tile 32)

    float acc[4][4][4];
#pragma unroll
    for (int mt = 0; mt < 4; mt++)
#pragma unroll
        for (int nt = 0; nt < 4; nt++)
#pragma unroll
            for (int j = 0; j < 4; j++) acc[mt][nt][j] = 0.0f;

    // ---- hoisted ldsm base addresses (loop-invariant) ----
    const int arow  = (lane & 7) + ((lane >> 3) & 1) * 8;
    const int ahalf = (lane >> 4) * 8;
    const int brow0 = (lane & 7) + ((lane >> 3) & 1) * 8;
    const int bcol0 = (lane >> 4) * 8;
    //  A addr(mt, ks, s) = aL0 + s*A_STAGE*2 + mt*(16*A_LD*2) + ks*32
    const uint32_t aL0 = smA + (uint32_t)((wm * 64 + arow) * A_LD + ahalf) * 2;
    //  B addr(np, ks, s) = bL0 + s*B_STAGE*2 + np*32 + ks*(16*B_LD*2)
    const uint32_t bL0 = smB + (uint32_t)(brow0 * B_LD + wn * 32 + bcol0) * 2;

    for (int kt = 0; kt < KT; ++kt) {
        // group kt done; groups kt+1, kt+2 may still be in flight (3-iter prefetch distance)
        asm volatile("cp.async.wait_group 2;\n" ::: "memory");
        __syncthreads();
        // loads at TOP of iteration (proven schedule); stage (kt+3)%4 consumed at kt-1 -> safe
        if (kt + 3 < KT) load_stage((kt + 3) % STAGES, kt + 3);
        asm volatile("cp.async.commit_group;\n" ::: "memory");

        const int s = kt % STAGES;
        const uint32_t aS = aL0 + (uint32_t)s * (A_STAGE * 2);
        const uint32_t bS = bL0 + (uint32_t)s * (B_STAGE * 2);

#pragma unroll
        for (int ks = 0; ks < 2; ++ks) {
            // B fragments: 32 cols = 2 x ldsm_x4t (8 regs)
            uint32_t bfr[4][2];
#pragma unroll
            for (int np = 0; np < 2; np++) {
                uint32_t r0, r1, r2, r3;
                ldsm_x4t(r0, r1, r2, r3, bS + np * 32 + ks * (16 * B_LD * 2));
                bfr[np * 2][0] = r0;     bfr[np * 2][1] = r1;
                bfr[np * 2 + 1][0] = r2; bfr[np * 2 + 1][1] = r3;
            }
            // A fragments one 16-row slab at a time, 4 mma each
#pragma unroll
            for (int mt = 0; mt < 4; mt++) {
                uint32_t af[4];
                ldsm_x4(af[0], af[1], af[2], af[3], aS + mt * (16 * A_LD * 2) + ks * 32);
#pragma unroll
                for (int nt = 0; nt < 4; nt++)
                    mma16816(acc[mt][nt], af, bfr[nt]);
            }
        }
    }
    asm volatile("cp.async.wait_group 0;\n" ::: "memory");

    const int rbase = m0 + wm * 64 + (lane >> 2);
    const int cbase = n0 + wn * 32 + (lane & 3) * 2;

    if (EPI == 0) {
#pragma unroll
        for (int mt = 0; mt < 4; mt++) {
#pragma unroll
            for (int nt = 0; nt < 4; nt++) {
                int r = rbase + mt * 16;
                int c = cbase + nt * 8;
                float b0 = bias[c], b1 = bias[c + 1];
                float v00 = fmaxf(acc[mt][nt][0] + b0, 0.0f);
                float v01 = fmaxf(acc[mt][nt][1] + b1, 0.0f);
                float v10 = fmaxf(acc[mt][nt][2] + b0, 0.0f);
                float v11 = fmaxf(acc[mt][nt][3] + b1, 0.0f);
                *(__nv_bfloat162*)&Cout[(size_t)r * N + c]       = __floats2bfloat162_rn(v00, v01);
                *(__nv_bfloat162*)&Cout[(size_t)(r + 8) * N + c] = __floats2bfloat162_rn(v10, v11);
            }
        }
    } else {
        // Head layout over N=2048: [0,512)->0, [512,1024)->1, [1024,2048)->2 (1024 wide!)
        const int head = (n0 >= 1024) ? 2 : (n0 >> 9);
        float s0[4], s1[4];
#pragma unroll
        for (int mt = 0; mt < 4; mt++) { s0[mt] = 0.0f; s1[mt] = 0.0f; }
#pragma unroll
        for (int mt = 0; mt < 4; mt++) {
#pragma unroll
            for (int nt = 0; nt < 4; nt++) {
                int c = cbase + nt * 8;
                float b0 = bhead[c], b1 = bhead[c + 1];
                float w0 = wvec[c],  w1 = wvec[c + 1];
                s0[mt] += fmaxf(acc[mt][nt][0] + b0, 0.0f) * w0 + fmaxf(acc[mt][nt][1] + b1, 0.0f) * w1;
                s1[mt] += fmaxf(acc[mt][nt][2] + b0, 0.0f) * w0 + fmaxf(acc[mt][nt][3] + b1, 0.0f) * w1;
            }
        }
#pragma unroll
        for (int mt = 0; mt < 4; mt++) {
            float v0 = s0[mt];
            v0 += __shfl_xor_sync(0xffffffffu, v0, 1);
            v0 += __shfl_xor_sync(0xffffffffu, v0, 2);
            float v1 = s1[mt];
            v1 += __shfl_xor_sync(0xffffffffu, v1, 1);
            v1 += __shfl_xor_sync(0xffffffffu, v1, 2);
            if ((lane & 3) == 0) {
                atomicAdd(&logits[(size_t)(rbase + mt * 16) * 3 + head], v0);
                atomicAdd(&logits[(size_t)(rbase + mt * 16 + 8) * 3 + head], v1);
            }
        }
    }
}

// ---------------- host ----------------
extern "C" void kernel_launch(void* const* d_in, const int* in_sizes, int n_in,
                              void* d_out, int out_size)
{
    const float* obs = (const float*)d_in[0];
    // d_in[1] = agent_positions (unused)
    const float* W1  = (const float*)d_in[2];
    const float* b1  = (const float*)d_in[3];
    const float* W2  = (const float*)d_in[4];
    const float* b2  = (const float*)d_in[5];
    const float* Wc1 = (const float*)d_in[6];
    const float* bc1 = (const float*)d_in[7];
    const float* Wc2 = (const float*)d_in[8];
    const float* bc2 = (const float*)d_in[9];
    const float* Wt1 = (const float*)d_in[10];
    const float* bt1 = (const float*)d_in[11];
    const float* Wt2 = (const float*)d_in[12];
    const float* bt2 = (const float*)d_in[13];
    const float* Wk1 = (const float*)d_in[14];
    const float* bk1 = (const float*)d_in[15];
    const float* Wk2 = (const float*)d_in[16];
    const float* bk2 = (const float*)d_in[17];
    float* out = (float*)d_out;

    void *pObs, *pW1, *pW2, *pWh, *pG1, *pG, *pWvec, *pBhead, *pLogits;
    cudaGetSymbolAddress(&pObs, g_obs);
    cudaGetSymbolAddress(&pW1, g_W1);
    cudaGetSymbolAddress(&pW2, g_W2);
    cudaGetSymbolAddress(&pWh, g_Wh);
    cudaGetSymbolAddress(&pG1, g_G1);
    cudaGetSymbolAddress(&pG, g_G);
    cudaGetSymbolAddress(&pWvec, g_wvec);
    cudaGetSymbolAddress(&pBhead, g_bhead);
    cudaGetSymbolAddress(&pLogits, g_logits);

    cudaFuncSetAttribute((const void*)gemm_bf16<0>,
                         cudaFuncAttributeMaxDynamicSharedMemorySize, SMEM_BYTES);
    cudaFuncSetAttribute((const void*)gemm_bf16<1>,
                         cudaFuncAttributeMaxDynamicSharedMemorySize, SMEM_BYTES);

    // prep weights + zero logits
    k_prep<<<(HD * NHEADCOLS + 255) / 256, 256>>>(W1, W2, Wc1, Wt1, Wk1, Wc2, Wt2, Wk2, bc1, bt1, bk1);
    k_conv_obs<<<(BQ * OBSD / 4 + 255) / 256, 256>>>((const float4*)obs, (__nv_bfloat162*)pObs);

    // GEMM1: G1 = relu(obs @ W1 + b1)   [16384,512]x[512,1024]
    gemm_bf16<0><<<dim3(HD / BN, BQ / BM), 256, SMEM_BYTES>>>(
        (const bf16*)pObs, (const bf16*)pW1, b1, (bf16*)pG1,
        nullptr, nullptr, nullptr, BQ, HD, OBSD);

    // GEMM2: G = relu(G1 @ W2 + b2)     [16384,1024]x[1024,1024]
    gemm_bf16<0><<<dim3(HD / BN, BQ / BM), 256, SMEM_BYTES>>>(
        (const bf16*)pG1, (const bf16*)pW2, b2, (bf16*)pG,
        nullptr, nullptr, nullptr, BQ, HD, HD);

    // GEMM3: heads, fused epilogue -> logits  [16384,1024]x[1024,2048]
    gemm_bf16<1><<<dim3(NHEADCOLS / BN, BQ / BM), 256, SMEM_BYTES>>>(
        (const bf16*)pG, (const bf16*)pWh, nullptr, nullptr,
        (const float*)pWvec, (const float*)pBhead, (float*)pLogits, BQ, NHEADCOLS, HD);

    // sigmoid + broadcast to [3][B, 9]
    k_final<<<(BQ + 255) / 256, 256>>>((const float*)pLogits, bc2, bt2, bk2, out);
}

// round 16
// speedup vs baseline: 1.5924x; 1.5924x over previous
#include <cuda_runtime.h>
#include <cuda_bf16.h>
#include <math.h>
#include <stdint.h>

typedef __nv_bfloat16 bf16;

#define BQ   16384
#define OBSD 512
#define HD   1024
#define NHEADCOLS 2048
#define NAG  9

// ---------------- scratch (device globals: no allocation allowed) ----------------
__device__ bf16  g_obs[BQ * OBSD];        // 16 MB
__device__ bf16  g_W1 [OBSD * HD];        // 1 MB
__device__ bf16  g_W2 [HD * HD];          // 2 MB
__device__ bf16  g_Wh [HD * NHEADCOLS];   // 4 MB  (Wc1 | Wt1 | Wk1[:H]+Wk1[H:])
__device__ bf16  g_G1 [BQ * HD];          // 32 MB
__device__ bf16  g_G  [BQ * HD];          // 32 MB
__device__ float g_wvec [NHEADCOLS];      // Wc2 | Wt2 | Wk2
__device__ float g_bhead[NHEADCOLS];      // bc1 | bt1 | bk1
__device__ float g_logits[BQ * 3];

// ---------------- fused prep: weights + bias vectors + logits zero + obs conversion ----------------
// NOTE: BQ*OBSD/4 == HD*NHEADCOLS == 2097152, so one grid covers both the Wh build and obs conv.
__global__ void k_prep(const float* __restrict__ W1, const float* __restrict__ W2,
                       const float* __restrict__ Wc1, const float* __restrict__ Wt1,
                       const float* __restrict__ Wk1,
                       const float* __restrict__ Wc2, const float* __restrict__ Wt2,
                       const float* __restrict__ Wk2,
                       const float* __restrict__ bc1, const float* __restrict__ bt1,
                       const float* __restrict__ bk1,
                       const float4* __restrict__ obs4)
{
    int i = blockIdx.x * blockDim.x + threadIdx.x;
    if (i < OBSD * HD) g_W1[i] = __float2bfloat16(W1[i]);
    if (i < HD * HD)   g_W2[i] = __float2bfloat16(W2[i]);
    if (i < HD * NHEADCOLS) {
        int k = i >> 11;        // row (0..1023)
        int j = i & 2047;       // col (0..2047)
        float v;
        if (j < 512)          v = Wc1[k * 512 + j];
        else if (j < 1024)    v = Wt1[k * 512 + (j - 512)];
        else                  v = Wk1[k * 1024 + (j - 1024)] + Wk1[(1024 + k) * 1024 + (j - 1024)];
        g_Wh[i] = __float2bfloat16(v);
    }
    if (i < BQ * OBSD / 4) {    // obs fp32 -> bf16 (same index space size as Wh job)
        float4 v = obs4[i];
        __nv_bfloat162* o = (__nv_bfloat162*)g_obs;
        o[2 * i]     = __floats2bfloat162_rn(v.x, v.y);
        o[2 * i + 1] = __floats2bfloat162_rn(v.z, v.w);
    }
    if (i < NHEADCOLS) {
        float wv, bh;
        if (i < 512)       { wv = Wc2[i];        bh = bc1[i]; }
        else if (i < 1024) { wv = Wt2[i - 512];  bh = bt1[i - 512]; }
        else               { wv = Wk2[i - 1024]; bh = bk1[i - 1024]; }
        g_wvec[i] = wv; g_bhead[i] = bh;
    }
    if (i < BQ * 3) g_logits[i] = 0.0f;
}

__global__ void k_final(const float* __restrict__ logits,
                        const float* __restrict__ bc2, const float* __restrict__ bt2,
                        const float* __restrict__ bk2, float* __restrict__ out)
{
    int b = blockIdx.x * blockDim.x + threadIdx.x;
    if (b >= BQ) return;
    float cv = 1.0f / (1.0f + expf(-(logits[b * 3 + 0] + bc2[0])));
    float tk = 1.0f / (1.0f + expf(-(logits[b * 3 + 1] + bt2[0])));
    float cp = 1.0f / (1.0f + expf(-(logits[b * 3 + 2] + bk2[0])));
#pragma unroll
    for (int n = 0; n < NAG; ++n) {
        out[(size_t)0 * BQ * NAG + b * NAG + n] = cv;
        out[(size_t)1 * BQ * NAG + b * NAG + n] = tk;
        out[(size_t)2 * BQ * NAG + b * NAG + n] = cp;
    }
}

// --- bf16 tensor-core GEMM: 128x128 CTA, 4 warps of 64x64, BK=32, 4 stages, 3 CTAs/SM ---
// (round-13 configuration: best measured gemm<0> = 100.5 us; all structural departures regressed)
#define BM 128
#define BN 128
#define BK 32
#define STAGES 4
#define A_LD 40               // 32 + 8 pad: 80B rows -> disjoint bank quads for 8-row ldmatrix
#define B_LD 136              // 128 + 8 pad
#define A_STAGE (BM * A_LD)   // 5120 elems
#define B_STAGE (BK * B_LD)   // 4352 elems
#define SMEM_BYTES (STAGES * (A_STAGE + B_STAGE) * 2)   // 75776 ; x3 CTAs = 227328 <= 228KB

__device__ __forceinline__ void cp16s(uint32_t dst, const void* src)
{
    asm volatile("cp.async.cg.shared.global [%0], [%1], 16;\n" :: "r"(dst), "l"(src));
}

__device__ __forceinline__ uint32_t smem_u32_of(const void* p)
{
    uint32_t a;
    asm("{ .reg .u64 t; cvta.to.shared.u64 t, %1; cvt.u32.u64 %0, t; }" : "=r"(a) : "l"(p));
    return a;
}

__device__ __forceinline__ void ldsm_x4(uint32_t& r0, uint32_t& r1, uint32_t& r2, uint32_t& r3, uint32_t addr)
{
    asm volatile("ldmatrix.sync.aligned.m8n8.x4.shared.b16 {%0,%1,%2,%3}, [%4];\n"
                 : "=r"(r0), "=r"(r1), "=r"(r2), "=r"(r3) : "r"(addr));
}

__device__ __forceinline__ void ldsm_x4t(uint32_t& r0, uint32_t& r1, uint32_t& r2, uint32_t& r3, uint32_t addr)
{
    asm volatile("ldmatrix.sync.aligned.m8n8.x4.trans.shared.b16 {%0,%1,%2,%3}, [%4];\n"
                 : "=r"(r0), "=r"(r1), "=r"(r2), "=r"(r3) : "r"(addr));
}

__device__ __forceinline__ void mma16816(float* c, const uint32_t* a, const uint32_t* b)
{
    asm volatile("mma.sync.aligned.m16n8k16.row.col.f32.bf16.bf16.f32 "
                 "{%0,%1,%2,%3}, {%4,%5,%6,%7}, {%8,%9}, {%0,%1,%2,%3};\n"
                 : "+f"(c[0]), "+f"(c[1]), "+f"(c[2]), "+f"(c[3])
                 : "r"(a[0]), "r"(a[1]), "r"(a[2]), "r"(a[3]), "r"(b[0]), "r"(b[1]));
}

// EPI 0: C = relu(acc + bias[col]) -> bf16 Cout[M,N]
// EPI 1: per-row partial dot of relu(acc + bhead[col]) with wvec[col], atomicAdd -> logits[row*3+head]
template <int EPI>
__global__ void __launch_bounds__(128, 3)
gemm_bf16(const bf16* __restrict__ A, const bf16* __restrict__ Bw,
          const float* __restrict__ bias, bf16* __restrict__ Cout,
          const float* __restrict__ wvec, const float* __restrict__ bhead,
          float* __restrict__ logits, int M, int N, int K)
{
    extern __shared__ __align__(16) bf16 smem[];
    bf16* As = smem;                     // STAGES * A_STAGE
    bf16* Bs = smem + STAGES * A_STAGE;  // STAGES * B_STAGE

    const int t  = threadIdx.x;
    const int n0 = blockIdx.x * BN;
    const int m0 = blockIdx.y * BM;
    const int KT = K / BK;

    const uint32_t smA = smem_u32_of(As);
    const uint32_t smB = smem_u32_of(Bs);

    // ---- hoisted loader addressing (per-thread, loop-invariant bases) ----
    const int arow_ld = t >> 2, acc_ld = t & 3;     // A: 4 chunks/row, +32 rows per i
    const int brow_ld = t >> 4, bcc_ld = t & 15;    // B: 16 chunks/row, +8 rows per i
    const uint32_t dA0 = smA + (uint32_t)(arow_ld * A_LD + acc_ld * 8) * 2;
    const uint32_t dB0 = smB + (uint32_t)(brow_ld * B_LD + bcc_ld * 8) * 2;
    const bf16* sA0 = A + (size_t)(m0 + arow_ld) * K + acc_ld * 8;
    const bf16* sB0 = Bw + (size_t)brow_ld * N + n0 + bcc_ld * 8;

    auto load_stage = [&](int s, int kt) {
        const uint32_t dA = dA0 + (uint32_t)s * (A_STAGE * 2);
        const bf16*    sA = sA0 + kt * BK;
#pragma unroll
        for (int i = 0; i < 4; i++)
            cp16s(dA + i * (32 * A_LD * 2), sA + (size_t)i * 32 * K);
        const uint32_t dB = dB0 + (uint32_t)s * (B_STAGE * 2);
        const bf16*    sB = sB0 + (size_t)kt * BK * N;
#pragma unroll
        for (int i = 0; i < 4; i++)
            cp16s(dB + i * (8 * B_LD * 2), sB + (size_t)i * 8 * N);
    };

    // prefetch 3 stages
    load_stage(0, 0);
    asm volatile("cp.async.commit_group;\n" ::: "memory");
    load_stage(1, 1);
    asm volatile("cp.async.commit_group;\n" ::: "memory");
    load_stage(2, 2);
    asm volatile("cp.async.commit_group;\n" ::: "memory");

    const int lane = t & 31;
    const int warp = t >> 5;
    const int wm = warp & 1;   // 2 warps along M (tile 64)
    const int wn = warp >> 1;  // 2 warps along N (tile 64)

    float acc[4][8][4];
#pragma unroll
    for (int mt = 0; mt < 4; mt++)
#pragma unroll
        for (int nt = 0; nt < 8; nt++)
#pragma unroll
            for (int j = 0; j < 4; j++) acc[mt][nt][j] = 0.0f;

    // ---- hoisted ldsm base addresses (loop-invariant) ----
    const int arow  = (lane & 7) + ((lane >> 3) & 1) * 8;
    const int ahalf = (lane >> 4) * 8;
    const int brow0 = (lane & 7) + ((lane >> 3) & 1) * 8;
    const int bcol0 = (lane >> 4) * 8;
    //  A addr(mt, ks, s) = aL0 + s*A_STAGE*2 + mt*(16*A_LD*2) + ks*32
    const uint32_t aL0 = smA + (uint32_t)((wm * 64 + arow) * A_LD + ahalf) * 2;
    //  B addr(np, ks, s) = bL0 + s*B_STAGE*2 + np*32 + ks*(16*B_LD*2)
    const uint32_t bL0 = smB + (uint32_t)(brow0 * B_LD + wn * 64 + bcol0) * 2;

    for (int kt = 0; kt < KT; ++kt) {
        // group kt done; groups kt+1, kt+2 may still be in flight (3-iter prefetch distance)
        asm volatile("cp.async.wait_group 2;\n" ::: "memory");
        __syncthreads();
        // loads at TOP of iteration (proven schedule; mid-iteration placement regressed in R12)
        // stage (kt+3)%4 was consumed at iteration kt-1; barrier above makes overwrite safe
        if (kt + 3 < KT) load_stage((kt + 3) % STAGES, kt + 3);
        asm volatile("cp.async.commit_group;\n" ::: "memory");

        const int s = kt % STAGES;
        const uint32_t aS = aL0 + (uint32_t)s * (A_STAGE * 2);
        const uint32_t bS = bL0 + (uint32_t)s * (B_STAGE * 2);

#pragma unroll
        for (int ks = 0; ks < 2; ++ks) {
            uint32_t bfr[8][2];
#pragma unroll
            for (int np = 0; np < 4; np++) {
                uint32_t r0, r1, r2, r3;
                ldsm_x4t(r0, r1, r2, r3, bS + np * 32 + ks * (16 * B_LD * 2));
                bfr[np * 2][0] = r0;     bfr[np * 2][1] = r1;
                bfr[np * 2 + 1][0] = r2; bfr[np * 2 + 1][1] = r3;
            }
#pragma unroll
            for (int mt = 0; mt < 4; mt++) {
                uint32_t af[4];
                ldsm_x4(af[0], af[1], af[2], af[3], aS + mt * (16 * A_LD * 2) + ks * 32);
#pragma unroll
                for (int nt = 0; nt < 8; nt++)
                    mma16816(acc[mt][nt], af, bfr[nt]);
            }
        }
    }
    asm volatile("cp.async.wait_group 0;\n" ::: "memory");

    const int rbase = m0 + wm * 64 + (lane >> 2);
    const int cbase = n0 + wn * 64 + (lane & 3) * 2;

    if (EPI == 0) {
#pragma unroll
        for (int mt = 0; mt < 4; mt++) {
#pragma unroll
            for (int nt = 0; nt < 8; nt++) {
                int r = rbase + mt * 16;
                int c = cbase + nt * 8;
                float b0 = bias[c], b1 = bias[c + 1];
                float v00 = fmaxf(acc[mt][nt][0] + b0, 0.0f);
                float v01 = fmaxf(acc[mt][nt][1] + b1, 0.0f);
                float v10 = fmaxf(acc[mt][nt][2] + b0, 0.0f);
                float v11 = fmaxf(acc[mt][nt][3] + b1, 0.0f);
                *(__nv_bfloat162*)&Cout[(size_t)r * N + c]       = __floats2bfloat162_rn(v00, v01);
                *(__nv_bfloat162*)&Cout[(size_t)(r + 8) * N + c] = __floats2bfloat162_rn(v10, v11);
            }
        }
    } else {
        // Head layout over N=2048: [0,512)->0, [512,1024)->1, [1024,2048)->2 (1024 wide!)
        const int head = (n0 >= 1024) ? 2 : (n0 >> 9);
        float s0[4], s1[4];
#pragma unroll
        for (int mt = 0; mt < 4; mt++) { s0[mt] = 0.0f; s1[mt] = 0.0f; }
#pragma unroll
        for (int mt = 0; mt < 4; mt++) {
#pragma unroll
            for (int nt = 0; nt < 8; nt++) {
                int c = cbase + nt * 8;
                float b0 = bhead[c], b1 = bhead[c + 1];
                float w0 = wvec[c],  w1 = wvec[c + 1];
                s0[mt] += fmaxf(acc[mt][nt][0] + b0, 0.0f) * w0 + fmaxf(acc[mt][nt][1] + b1, 0.0f) * w1;
                s1[mt] += fmaxf(acc[mt][nt][2] + b0, 0.0f) * w0 + fmaxf(acc[mt][nt][3] + b1, 0.0f) * w1;
            }
        }
#pragma unroll
        for (int mt = 0; mt < 4; mt++) {
            float v0 = s0[mt];
            v0 += __shfl_xor_sync(0xffffffffu, v0, 1);
            v0 += __shfl_xor_sync(0xffffffffu, v0, 2);
            float v1 = s1[mt];
            v1 += __shfl_xor_sync(0xffffffffu, v1, 1);
            v1 += __shfl_xor_sync(0xffffffffu, v1, 2);
            if ((lane & 3) == 0) {
                atomicAdd(&logits[(size_t)(rbase + mt * 16) * 3 + head], v0);
                atomicAdd(&logits[(size_t)(rbase + mt * 16 + 8) * 3 + head], v1);
            }
        }
    }
}

// ---------------- host ----------------
extern "C" void kernel_launch(void* const* d_in, const int* in_sizes, int n_in,
                              void* d_out, int out_size)
{
    const float* obs = (const float*)d_in[0];
    // d_in[1] = agent_positions (unused)
    const float* W1  = (const float*)d_in[2];
    const float* b1  = (const float*)d_in[3];
    const float* W2  = (const float*)d_in[4];
    const float* b2  = (const float*)d_in[5];
    const float* Wc1 = (const float*)d_in[6];
    const float* bc1 = (const float*)d_in[7];
    const float* Wc2 = (const float*)d_in[8];
    const float* bc2 = (const float*)d_in[9];
    const float* Wt1 = (const float*)d_in[10];
    const float* bt1 = (const float*)d_in[11];
    const float* Wt2 = (const float*)d_in[12];
    const float* bt2 = (const float*)d_in[13];
    const float* Wk1 = (const float*)d_in[14];
    const float* bk1 = (const float*)d_in[15];
    const float* Wk2 = (const float*)d_in[16];
    const float* bk2 = (const float*)d_in[17];
    float* out = (float*)d_out;

    void *pObs, *pW1, *pW2, *pWh, *pG1, *pG, *pWvec, *pBhead, *pLogits;
    cudaGetSymbolAddress(&pObs, g_obs);
    cudaGetSymbolAddress(&pW1, g_W1);
    cudaGetSymbolAddress(&pW2, g_W2);
    cudaGetSymbolAddress(&pWh, g_Wh);
    cudaGetSymbolAddress(&pG1, g_G1);
    cudaGetSymbolAddress(&pG, g_G);
    cudaGetSymbolAddress(&pWvec, g_wvec);
    cudaGetSymbolAddress(&pBhead, g_bhead);
    cudaGetSymbolAddress(&pLogits, g_logits);

    cudaFuncSetAttribute((const void*)gemm_bf16<0>,
                         cudaFuncAttributeMaxDynamicSharedMemorySize, SMEM_BYTES);
    cudaFuncSetAttribute((const void*)gemm_bf16<1>,
                         cudaFuncAttributeMaxDynamicSharedMemorySize, SMEM_BYTES);

    // fused prep: weights + head vectors + logits zero + obs conversion (one launch)
    k_prep<<<(HD * NHEADCOLS + 255) / 256, 256>>>(W1, W2, Wc1, Wt1, Wk1, Wc2, Wt2, Wk2,
                                                  bc1, bt1, bk1, (const float4*)obs);

    // GEMM1: G1 = relu(obs @ W1 + b1)   [16384,512]x[512,1024]
    gemm_bf16<0><<<dim3(HD / BN, BQ / BM), 128, SMEM_BYTES>>>(
        (const bf16*)pObs, (const bf16*)pW1, b1, (bf16*)pG1,
        nullptr, nullptr, nullptr, BQ, HD, OBSD);

    // GEMM2: G = relu(G1 @ W2 + b2)     [16384,1024]x[1024,1024]
    gemm_bf16<0><<<dim3(HD / BN, BQ / BM), 128, SMEM_BYTES>>>(
        (const bf16*)pG1, (const bf16*)pW2, b2, (bf16*)pG,
        nullptr, nullptr, nullptr, BQ, HD, HD);

    // GEMM3: heads, fused epilogue -> logits  [16384,1024]x[1024,2048]
    gemm_bf16<1><<<dim3(NHEADCOLS / BN, BQ / BM), 128, SMEM_BYTES>>>(
        (const bf16*)pG, (const bf16*)pWh, nullptr, nullptr,
        (const float*)pWvec, (const float*)pBhead, (float*)pLogits, BQ, NHEADCOLS, HD);

    // sigmoid + broadcast to [3][B, 9]
    k_final<<<(BQ + 255) / 256, 256>>>((const float*)pLogits, bc2, bt2, bk2, out);
}